// round 1
// baseline (speedup 1.0000x reference)
#include <cuda_runtime.h>
#include <math.h>

// ---------------------------------------------------------------------------
// TT feed-forward:  out = (GELU(x @ W1 + b1)) @ W2 + b2
// W1 [1024,4096], W2 [4096,1024] materialized from TT cores each launch.
// Scratch in __device__ globals (allowed; no runtime allocation).
// ---------------------------------------------------------------------------

__device__ float g_P [128 * 256 * 16];   // pair contraction buffer (2 MB), reused
__device__ float g_W1[1024 * 4096];      // 16 MB
__device__ float g_W2[4096 * 1024];      // 16 MB
__device__ float g_H [4096 * 4096];      // 64 MB hidden activations

// ---------------------------------------------------------------------------
// P[pair=(n1*M1+m1)][j=(n2*16+m2)][r2] = sum_r1 c0[n1,m1,r1] * c1[r1,n2,m2,r2]
// pair count is always 128 (8*16 or 16*8), c1 is always [16,16,16,16].
// ---------------------------------------------------------------------------
__global__ void pair_kernel(const float* __restrict__ c0,
                            const float* __restrict__ c1)
{
    int idx  = blockIdx.x * blockDim.x + threadIdx.x;   // 524288 total
    int r2   = idx & 15;
    int j    = (idx >> 4) & 255;
    int pair = idx >> 12;
    const float* c0p = c0 + pair * 16;
    float acc = 0.f;
#pragma unroll
    for (int r1 = 0; r1 < 16; ++r1)
        acc += c0p[r1] * c1[(r1 * 256 + j) * 16 + r2];
    g_P[idx] = acc;
}

// ---------------------------------------------------------------------------
// W1[n,m]: n = n1*128 + n2*8 + n3  (in dims 8,16,8)
//          m = m1*256 + m2*16 + m3 (out dims 16,16,16)
// c2: [r2][n3][m3] = [16][8][16]
// ---------------------------------------------------------------------------
__global__ void w1_kernel(const float* __restrict__ c2)
{
    __shared__ float s_c2[16 * 8 * 16];
    for (int i = threadIdx.x; i < 2048; i += blockDim.x) s_c2[i] = c2[i];
    __syncthreads();

    int idx = blockIdx.x * blockDim.x + threadIdx.x;    // 1024*4096
    int m = idx & 4095;
    int n = idx >> 12;
    int n1 = n >> 7, n2 = (n >> 3) & 15, n3 = n & 7;
    int m1 = m >> 8, m2 = (m >> 4) & 15, m3 = m & 15;
    const float* p = g_P + (((n1 * 16 + m1) * 256) + (n2 * 16 + m2)) * 16;
    float acc = 0.f;
#pragma unroll
    for (int r2 = 0; r2 < 16; ++r2)
        acc += p[r2] * s_c2[(r2 * 8 + n3) * 16 + m3];
    g_W1[idx] = acc;
}

// ---------------------------------------------------------------------------
// W2[n,m]: n = n1*256 + n2*16 + n3 (in dims 16,16,16)
//          m = m1*128 + m2*8 + m3  (out dims 8,16,8)
// c2: [r2][n3][m3] = [16][16][8]
// ---------------------------------------------------------------------------
__global__ void w2_kernel(const float* __restrict__ c2)
{
    __shared__ float s_c2[16 * 16 * 8];
    for (int i = threadIdx.x; i < 2048; i += blockDim.x) s_c2[i] = c2[i];
    __syncthreads();

    int idx = blockIdx.x * blockDim.x + threadIdx.x;    // 4096*1024
    int m = idx & 1023;
    int n = idx >> 10;
    int n1 = n >> 8, n2 = (n >> 4) & 15, n3 = n & 15;
    int m1 = m >> 7, m2 = (m >> 3) & 15, m3 = m & 7;
    const float* p = g_P + (((n1 * 8 + m1) * 256) + (n2 * 16 + m2)) * 16;
    float acc = 0.f;
#pragma unroll
    for (int r2 = 0; r2 < 16; ++r2)
        acc += p[r2] * s_c2[(r2 * 16 + n3) * 8 + m3];
    g_W2[idx] = acc;
}

// ---------------------------------------------------------------------------
// fp32 SGEMM: C[M,N] = A[M,K] * B[K,N] + bias[N], optional exact-erf GELU.
// 128x128 block tile, BK=16, 256 threads, 8x8 per thread, double-buffered smem.
// All dims are multiples of tile sizes (M=4096, N in {4096,1024}, K in {1024,4096}).
// ---------------------------------------------------------------------------
__global__ void __launch_bounds__(256) sgemm128(
    const float* __restrict__ A, const float* __restrict__ B,
    const float* __restrict__ bias, float* __restrict__ C,
    int M, int N, int K, int fuse_gelu)
{
    const int BM = 128, BN = 128, BK = 16;
    __shared__ float As[2][BK][BM];   // transposed: As[k][row]
    __shared__ float Bs[2][BK][BN];   // Bs[k][col]

    int tid = threadIdx.x;
    int ty = tid >> 4;              // 0..15
    int tx = tid & 15;              // 0..15
    int rowBase = blockIdx.y * BM;
    int colBase = blockIdx.x * BN;

    // global-load assignments
    int aRow = tid >> 2;            // 0..63 (+64 for second half)
    int aCol = (tid & 3) << 2;      // 0,4,8,12
    int bRow = tid >> 5;            // 0..7 (+8 for second half)
    int bCol = (tid & 31) << 2;     // 0..124

    const float* Aptr = A + (size_t)(rowBase + aRow) * K + aCol;
    const float* Bptr = B + (size_t)bRow * N + colBase + bCol;

    float4 aReg0, aReg1, bReg0, bReg1;
    float acc[8][8] = {};

    int nT = K / BK;

    // prologue: tile 0 -> regs -> smem buf 0
    aReg0 = *(const float4*)(Aptr);
    aReg1 = *(const float4*)(Aptr + (size_t)64 * K);
    bReg0 = *(const float4*)(Bptr);
    bReg1 = *(const float4*)(Bptr + (size_t)8 * N);

    As[0][aCol + 0][aRow]      = aReg0.x;
    As[0][aCol + 1][aRow]      = aReg0.y;
    As[0][aCol + 2][aRow]      = aReg0.z;
    As[0][aCol + 3][aRow]      = aReg0.w;
    As[0][aCol + 0][aRow + 64] = aReg1.x;
    As[0][aCol + 1][aRow + 64] = aReg1.y;
    As[0][aCol + 2][aRow + 64] = aReg1.z;
    As[0][aCol + 3][aRow + 64] = aReg1.w;
    *(float4*)&Bs[0][bRow][bCol]     = bReg0;
    *(float4*)&Bs[0][bRow + 8][bCol] = bReg1;
    __syncthreads();

    int buf = 0;
    for (int kt = 0; kt < nT; ++kt) {
        if (kt + 1 < nT) {
            const float* Ap = Aptr + (kt + 1) * BK;
            aReg0 = *(const float4*)(Ap);
            aReg1 = *(const float4*)(Ap + (size_t)64 * K);
            const float* Bp = Bptr + (size_t)(kt + 1) * BK * N;
            bReg0 = *(const float4*)(Bp);
            bReg1 = *(const float4*)(Bp + (size_t)8 * N);
        }

#pragma unroll
        for (int kk = 0; kk < BK; ++kk) {
            float ra[8], rb[8];
            *(float4*)&ra[0] = *(const float4*)&As[buf][kk][ty * 8];
            *(float4*)&ra[4] = *(const float4*)&As[buf][kk][ty * 8 + 4];
            *(float4*)&rb[0] = *(const float4*)&Bs[buf][kk][tx * 8];
            *(float4*)&rb[4] = *(const float4*)&Bs[buf][kk][tx * 8 + 4];
#pragma unroll
            for (int i = 0; i < 8; ++i)
#pragma unroll
                for (int j = 0; j < 8; ++j)
                    acc[i][j] += ra[i] * rb[j];
        }

        if (kt + 1 < nT) {
            buf ^= 1;
            As[buf][aCol + 0][aRow]      = aReg0.x;
            As[buf][aCol + 1][aRow]      = aReg0.y;
            As[buf][aCol + 2][aRow]      = aReg0.z;
            As[buf][aCol + 3][aRow]      = aReg0.w;
            As[buf][aCol + 0][aRow + 64] = aReg1.x;
            As[buf][aCol + 1][aRow + 64] = aReg1.y;
            As[buf][aCol + 2][aRow + 64] = aReg1.z;
            As[buf][aCol + 3][aRow + 64] = aReg1.w;
            *(float4*)&Bs[buf][bRow][bCol]     = bReg0;
            *(float4*)&Bs[buf][bRow + 8][bCol] = bReg1;
            __syncthreads();
        }
    }

    // epilogue: bias (+ exact-erf GELU), vectorized stores
    int row0 = rowBase + ty * 8;
    int col0 = colBase + tx * 8;
#pragma unroll
    for (int i = 0; i < 8; ++i) {
#pragma unroll
        for (int j = 0; j < 8; ++j) {
            float z = acc[i][j] + bias[col0 + j];
            if (fuse_gelu)
                z = 0.5f * z * (1.0f + erff(z * 0.70710678118654752f));
            acc[i][j] = z;
        }
        *(float4*)&C[(size_t)(row0 + i) * N + col0]     = *(float4*)&acc[i][0];
        *(float4*)&C[(size_t)(row0 + i) * N + col0 + 4] = *(float4*)&acc[i][4];
    }
}

// ---------------------------------------------------------------------------
// Launch: pair1 -> W1 -> pair2 -> W2 -> GEMM1(+GELU) -> GEMM2
// All on the capture stream, linearly ordered.
// ---------------------------------------------------------------------------
extern "C" void kernel_launch(void* const* d_in, const int* in_sizes, int n_in,
                              void* d_out, int out_size)
{
    const float* x   = (const float*)d_in[0];
    const float* c10 = (const float*)d_in[1];
    const float* c11 = (const float*)d_in[2];
    const float* c12 = (const float*)d_in[3];
    const float* b1  = (const float*)d_in[4];
    const float* c20 = (const float*)d_in[5];
    const float* c21 = (const float*)d_in[6];
    const float* c22 = (const float*)d_in[7];
    const float* b2  = (const float*)d_in[8];
    float* out = (float*)d_out;

    float *pW1, *pW2, *pH;
    cudaGetSymbolAddress((void**)&pW1, g_W1);
    cudaGetSymbolAddress((void**)&pW2, g_W2);
    cudaGetSymbolAddress((void**)&pH,  g_H);

    // Materialize W1
    pair_kernel<<<2048, 256>>>(c10, c11);
    w1_kernel<<<16384, 256>>>(c12);
    // Materialize W2 (reuses g_P; stream order serializes)
    pair_kernel<<<2048, 256>>>(c20, c21);
    w2_kernel<<<16384, 256>>>(c22);

    // GEMM1: H = GELU(x @ W1 + b1)   [4096,1024]x[1024,4096]
    dim3 g1(4096 / 128, 4096 / 128);
    sgemm128<<<g1, 256>>>(x, pW1, b1, pH, 4096, 4096, 1024, 1);

    // GEMM2: out = H @ W2 + b2       [4096,4096]x[4096,1024]
    dim3 g2(1024 / 128, 4096 / 128);
    sgemm128<<<g2, 256>>>(pH, pW2, b2, out, 4096, 1024, 4096, 0);
}

// round 3
// speedup vs baseline: 2.8857x; 2.8857x over previous
#include <cuda_runtime.h>
#include <math.h>
#include <stdint.h>

// ---------------------------------------------------------------------------
// TT feed-forward via dense weight materialization + tf32 mma.sync GEMMs.
// (tcgen05 is unavailable: harness PTX virtual arch is compute_103, not 103a.)
//   W1t[4096,1024], W2t[1024,4096]  (transposed, tf32-rounded)
//   Xr  = tf32(x)
//   H   = tf32(GELU(Xr @ W1t^T + b1))
//   out = H @ W2t^T + b2
// ---------------------------------------------------------------------------

__device__ float g_P  [128 * 256 * 16];      // 2 MB pair buffer (reused)
__device__ float g_W1t[4096 * 1024];         // [hidden, embed]
__device__ float g_W2t[1024 * 4096];         // [embed, hidden]
__device__ float g_H  [4096 * 4096];         // hidden activations
__device__ float g_Xr [4096 * 1024];         // tf32-rounded x

// ------------------------------ helpers -----------------------------------
__device__ __forceinline__ uint32_t smem_u32(const void* p) {
    uint32_t a;
    asm("{ .reg .u64 t; cvta.to.shared.u64 t, %1; cvt.u32.u64 %0, t; }"
        : "=r"(a) : "l"(p));
    return a;
}
__device__ __forceinline__ float to_tf32(float f) {
    uint32_t u;
    asm("cvt.rna.tf32.f32 %0, %1;" : "=r"(u) : "f"(f));
    return __uint_as_float(u);
}
__device__ __forceinline__ void cp16(uint32_t dst, const void* src) {
    asm volatile("cp.async.cg.shared.global [%0], [%1], 16;"
                 :: "r"(dst), "l"(src));
}
#define CP_COMMIT() asm volatile("cp.async.commit_group;")
#define CP_WAIT(n)  asm volatile("cp.async.wait_group %0;" :: "n"(n))

__device__ __forceinline__ void mma_tf32(float c[4], const uint32_t a[4],
                                         const uint32_t b[2]) {
    asm volatile(
        "mma.sync.aligned.m16n8k8.row.col.f32.tf32.tf32.f32 "
        "{%0,%1,%2,%3}, {%4,%5,%6,%7}, {%8,%9}, {%0,%1,%2,%3};"
        : "+f"(c[0]), "+f"(c[1]), "+f"(c[2]), "+f"(c[3])
        : "r"(a[0]), "r"(a[1]), "r"(a[2]), "r"(a[3]), "r"(b[0]), "r"(b[1]));
}

// ------------------------- weight materialization -------------------------
// P[pair][j][r2] = sum_r1 c0[pair, r1] * c1[r1, j, r2]   (pair=128, j=256, r2=16)
__global__ void pair_kernel(const float* __restrict__ c0,
                            const float* __restrict__ c1) {
    int idx  = blockIdx.x * blockDim.x + threadIdx.x;
    int r2   = idx & 15;
    int j    = (idx >> 4) & 255;
    int pair = idx >> 12;
    const float* c0p = c0 + pair * 16;
    float acc = 0.f;
#pragma unroll
    for (int r1 = 0; r1 < 16; ++r1)
        acc += c0p[r1] * c1[(r1 * 256 + j) * 16 + r2];
    g_P[idx] = acc;
}

// W1t[m, n]: m in [0,4096) hidden (16,16,16), n in [0,1024) embed (8,16,8)
__global__ void w1t_kernel(const float* __restrict__ c2) {
    __shared__ float s[16 * 16 * 8];   // [r2][m3][n3]
    for (int i = threadIdx.x; i < 2048; i += blockDim.x) {
        int r2 = i >> 7, n3 = (i >> 4) & 7, m3 = i & 15;   // c2: [r2][n3][m3]
        s[(r2 * 16 + m3) * 8 + n3] = c2[i];
    }
    __syncthreads();
    int idx = blockIdx.x * blockDim.x + threadIdx.x;    // 4096*1024
    int n = idx & 1023;
    int m = idx >> 10;
    int n1 = n >> 7, n2 = (n >> 3) & 15, n3 = n & 7;
    int m1 = m >> 8, m2 = (m >> 4) & 15, m3 = m & 15;
    const float* p = g_P + (((n1 * 16 + m1) * 256) + (n2 * 16 + m2)) * 16;
    float acc = 0.f;
#pragma unroll
    for (int r2 = 0; r2 < 16; ++r2)
        acc += p[r2] * s[(r2 * 16 + m3) * 8 + n3];
    g_W1t[idx] = to_tf32(acc);
}

// W2t[m, n]: m in [0,1024) embed (8,16,8), n in [0,4096) hidden (16,16,16)
__global__ void w2t_kernel(const float* __restrict__ c2) {
    __shared__ float s[16 * 8 * 16];   // [r2][m3][n3]
    for (int i = threadIdx.x; i < 2048; i += blockDim.x) {
        int r2 = i >> 7, n3 = (i >> 3) & 15, m3 = i & 7;   // c2: [r2][n3][m3]
        s[(r2 * 8 + m3) * 16 + n3] = c2[i];
    }
    __syncthreads();
    int idx = blockIdx.x * blockDim.x + threadIdx.x;    // 1024*4096
    int n = idx & 4095;
    int m = idx >> 12;
    int n1 = n >> 8, n2 = (n >> 4) & 15, n3 = n & 15;
    int m1 = m >> 7, m2 = (m >> 3) & 15, m3 = m & 7;
    const float* p = g_P + (((n1 * 8 + m1) * 256) + (n2 * 16 + m2)) * 16;
    float acc = 0.f;
#pragma unroll
    for (int r2 = 0; r2 < 16; ++r2)
        acc += p[r2] * s[(r2 * 8 + m3) * 16 + n3];
    g_W2t[idx] = to_tf32(acc);
}

__global__ void xround_kernel(const float4* __restrict__ x, float4* __restrict__ o) {
    int i = blockIdx.x * blockDim.x + threadIdx.x;      // 1048576 float4
    float4 v = x[i];
    v.x = to_tf32(v.x); v.y = to_tf32(v.y);
    v.z = to_tf32(v.z); v.w = to_tf32(v.w);
    o[i] = v;
}

// ------------------------------- tf32 GEMM --------------------------------
// C[M,N] = A[M,K] * B[N,K]^T + bias.  fuse=1: C = tf32(gelu_exact(.)).
// 128x128 CTA tile, BK=32, 256 threads (8 warps, warp tile 64x32),
// double-buffered cp.async, padded smem (36 floats/row -> conflict-free LDS).
#define SPAD 36
#define SBUF (128 * SPAD)   // floats per buffer per operand

__global__ void __launch_bounds__(256, 2) gemm_tf32(
    const float* __restrict__ A, const float* __restrict__ B,
    const float* __restrict__ bias, float* __restrict__ C,
    int K, int N, int fuse) {
    extern __shared__ float sm[];
    float* sA = sm;               // [2][128][SPAD]
    float* sB = sm + 2 * SBUF;    // [2][128][SPAD]
    uint32_t sAu = smem_u32(sA);
    uint32_t sBu = smem_u32(sB);

    int tid  = threadIdx.x;
    int lane = tid & 31;
    int q    = lane & 3;          // threadID in group
    int g8   = lane >> 2;         // group id 0..7
    int warp = tid >> 5;
    int wm   = (warp & 1) * 64;
    int wn   = (warp >> 1) * 32;

    size_t rowBase = (size_t)blockIdx.y * 128;
    size_t colBase = (size_t)blockIdx.x * 128;
    const float* Ag = A + rowBase * (size_t)K;
    const float* Bg = B + colBase * (size_t)K;

    int ldRow = tid >> 1;                 // base row for chunk id = tid + 256*i
    (void)ldRow;

#define LOAD_STAGE(s) do {                                                   \
    int buf = (s) & 1;                                                       \
    size_t koff = (size_t)(s) * 32;                                          \
    _Pragma("unroll")                                                        \
    for (int i = 0; i < 4; ++i) {                                            \
        int id = tid + 256 * i;                                              \
        int r = id >> 3, c4 = (id & 7) * 4;                                  \
        cp16(sAu + (buf * SBUF + r * SPAD + c4) * 4,                         \
             Ag + (size_t)r * K + koff + c4);                                \
        cp16(sBu + (buf * SBUF + r * SPAD + c4) * 4,                         \
             Bg + (size_t)r * K + koff + c4);                                \
    }                                                                        \
    CP_COMMIT();                                                             \
} while (0)

    float acc[4][4][4];
#pragma unroll
    for (int i = 0; i < 4; ++i)
#pragma unroll
        for (int j = 0; j < 4; ++j)
#pragma unroll
            for (int k = 0; k < 4; ++k) acc[i][j][k] = 0.f;

    int nS = K >> 5;
    LOAD_STAGE(0);

    for (int s = 0; s < nS; ++s) {
        if (s + 1 < nS) {
            LOAD_STAGE(s + 1);
            CP_WAIT(1);
        } else {
            CP_WAIT(0);
        }
        __syncthreads();

        const float* a = sA + (s & 1) * SBUF;
        const float* b = sB + (s & 1) * SBUF;
#pragma unroll
        for (int ks = 0; ks < 4; ++ks) {
            int k0 = ks * 8;
            uint32_t af[4][4], bf[4][2];
#pragma unroll
            for (int mt = 0; mt < 4; ++mt) {
                int r = wm + mt * 16 + g8;
                af[mt][0] = __float_as_uint(a[r * SPAD + k0 + q]);
                af[mt][1] = __float_as_uint(a[(r + 8) * SPAD + k0 + q]);
                af[mt][2] = __float_as_uint(a[r * SPAD + k0 + q + 4]);
                af[mt][3] = __float_as_uint(a[(r + 8) * SPAD + k0 + q + 4]);
            }
#pragma unroll
            for (int nt = 0; nt < 4; ++nt) {
                int c = wn + nt * 8 + g8;
                bf[nt][0] = __float_as_uint(b[c * SPAD + k0 + q]);
                bf[nt][1] = __float_as_uint(b[c * SPAD + k0 + q + 4]);
            }
#pragma unroll
            for (int mt = 0; mt < 4; ++mt)
#pragma unroll
                for (int nt = 0; nt < 4; ++nt)
                    mma_tf32(acc[mt][nt], af[mt], bf[nt]);
        }
        __syncthreads();
    }

    // ---- epilogue: bias (+ exact-erf GELU + tf32 round), float2 stores ----
#pragma unroll
    for (int nt = 0; nt < 4; ++nt) {
        int col = (int)colBase + wn + nt * 8 + 2 * q;
        float bx = bias[col], by = bias[col + 1];
#pragma unroll
        for (int mt = 0; mt < 4; ++mt) {
            size_t row0 = rowBase + wm + mt * 16 + g8;
            float v0 = acc[mt][nt][0] + bx;
            float v1 = acc[mt][nt][1] + by;
            float v2 = acc[mt][nt][2] + bx;
            float v3 = acc[mt][nt][3] + by;
            if (fuse) {
                v0 = to_tf32(0.5f * v0 * (1.0f + erff(v0 * 0.70710678118654752f)));
                v1 = to_tf32(0.5f * v1 * (1.0f + erff(v1 * 0.70710678118654752f)));
                v2 = to_tf32(0.5f * v2 * (1.0f + erff(v2 * 0.70710678118654752f)));
                v3 = to_tf32(0.5f * v3 * (1.0f + erff(v3 * 0.70710678118654752f)));
            }
            float2 lo = make_float2(v0, v1), hi = make_float2(v2, v3);
            *(float2*)&C[row0 * (size_t)N + col]       = lo;
            *(float2*)&C[(row0 + 8) * (size_t)N + col] = hi;
        }
    }
#undef LOAD_STAGE
}

// --------------------------------- launch ---------------------------------
extern "C" void kernel_launch(void* const* d_in, const int* in_sizes, int n_in,
                              void* d_out, int out_size) {
    const float* x   = (const float*)d_in[0];
    const float* c10 = (const float*)d_in[1];
    const float* c11 = (const float*)d_in[2];
    const float* c12 = (const float*)d_in[3];
    const float* b1  = (const float*)d_in[4];
    const float* c20 = (const float*)d_in[5];
    const float* c21 = (const float*)d_in[6];
    const float* c22 = (const float*)d_in[7];
    const float* b2  = (const float*)d_in[8];
    float* out = (float*)d_out;

    float *pW1t, *pW2t, *pH, *pXr;
    cudaGetSymbolAddress((void**)&pW1t, g_W1t);
    cudaGetSymbolAddress((void**)&pW2t, g_W2t);
    cudaGetSymbolAddress((void**)&pH,   g_H);
    cudaGetSymbolAddress((void**)&pXr,  g_Xr);

    const int SMEM = 4 * SBUF * sizeof(float);   // 73728 B
    cudaFuncSetAttribute(gemm_tf32, cudaFuncAttributeMaxDynamicSharedMemorySize,
                         SMEM);

    // tf32-round x
    xround_kernel<<<4096, 256>>>((const float4*)x, (float4*)pXr);

    // materialize W1t, W2t (tf32-rounded, transposed)
    pair_kernel<<<2048, 256>>>(c10, c11);
    w1t_kernel<<<16384, 256>>>(c12);
    pair_kernel<<<2048, 256>>>(c20, c21);
    w2t_kernel<<<16384, 256>>>(c22);

    // GEMM1: H = tf32(GELU(Xr @ W1t^T + b1))   [4096,1024] x [4096,1024]^T
    gemm_tf32<<<dim3(32, 32), 256, SMEM>>>(pXr, pW1t, b1, pH, 1024, 4096, 1);
    // GEMM2: out = H @ W2t^T + b2              [4096,4096] x [1024,4096]^T
    gemm_tf32<<<dim3(8, 32), 256, SMEM>>>(pH, pW2t, b2, out, 4096, 1024, 0);
}

// round 4
// speedup vs baseline: 3.9881x; 1.3820x over previous
#include <cuda_runtime.h>
#include <math.h>
#include <stdint.h>

// ---------------------------------------------------------------------------
// TT feed-forward via dense weight materialization + tf32 mma.sync GEMMs,
// ldmatrix fragment loads, 3-stage cp.async pipeline.
//   W1t[4096,1024], W2t[1024,4096]  (transposed, tf32-rounded)
//   Xr  = tf32(x);  H = tf32(GELU(Xr @ W1t^T + b1));  out = H @ W2t^T + b2
// ---------------------------------------------------------------------------

__device__ float g_P  [128 * 256 * 16];
__device__ float g_W1t[4096 * 1024];
__device__ float g_W2t[1024 * 4096];
__device__ float g_H  [4096 * 4096];
__device__ float g_Xr [4096 * 1024];

// ------------------------------ helpers -----------------------------------
__device__ __forceinline__ uint32_t smem_u32(const void* p) {
    uint32_t a;
    asm("{ .reg .u64 t; cvta.to.shared.u64 t, %1; cvt.u32.u64 %0, t; }"
        : "=r"(a) : "l"(p));
    return a;
}
__device__ __forceinline__ float to_tf32(float f) {
    uint32_t u;
    asm("cvt.rna.tf32.f32 %0, %1;" : "=r"(u) : "f"(f));
    return __uint_as_float(u);
}
__device__ __forceinline__ void cp16(uint32_t dst, const void* src) {
    asm volatile("cp.async.cg.shared.global [%0], [%1], 16;"
                 :: "r"(dst), "l"(src));
}
#define CP_COMMIT() asm volatile("cp.async.commit_group;")
#define CP_WAIT(n)  asm volatile("cp.async.wait_group %0;" :: "n"(n))

__device__ __forceinline__ void mma_tf32(float c[4], const uint32_t a[4],
                                         const uint32_t b[2]) {
    asm volatile(
        "mma.sync.aligned.m16n8k8.row.col.f32.tf32.tf32.f32 "
        "{%0,%1,%2,%3}, {%4,%5,%6,%7}, {%8,%9}, {%0,%1,%2,%3};"
        : "+f"(c[0]), "+f"(c[1]), "+f"(c[2]), "+f"(c[3])
        : "r"(a[0]), "r"(a[1]), "r"(a[2]), "r"(a[3]), "r"(b[0]), "r"(b[1]));
}
__device__ __forceinline__ void ldsm4(uint32_t& r0, uint32_t& r1,
                                      uint32_t& r2, uint32_t& r3,
                                      uint32_t addr) {
    asm volatile("ldmatrix.sync.aligned.m8n8.x4.shared.b16 {%0,%1,%2,%3}, [%4];"
                 : "=r"(r0), "=r"(r1), "=r"(r2), "=r"(r3) : "r"(addr));
}

// ------------------------- weight materialization -------------------------
// P[pair][j][r2] = sum_r1 c0[pair*16+r1] * c1[(r1*256+j)*16+r2]
// one thread -> 16 outputs (all r2), float4 I/O.
__global__ void pair_kernel(const float* __restrict__ c0,
                            const float* __restrict__ c1) {
    int idx  = blockIdx.x * blockDim.x + threadIdx.x;   // 32768
    int j    = idx & 255;
    int pair = idx >> 8;
    const float* c0p = c0 + pair * 16;
    float4 a0 = make_float4(0, 0, 0, 0), a1 = a0, a2 = a0, a3 = a0;
#pragma unroll
    for (int r1 = 0; r1 < 16; ++r1) {
        float w = c0p[r1];
        const float4* cp = (const float4*)(c1 + (r1 * 256 + j) * 16);
        float4 v0 = cp[0], v1 = cp[1], v2 = cp[2], v3 = cp[3];
        a0.x += w * v0.x; a0.y += w * v0.y; a0.z += w * v0.z; a0.w += w * v0.w;
        a1.x += w * v1.x; a1.y += w * v1.y; a1.z += w * v1.z; a1.w += w * v1.w;
        a2.x += w * v2.x; a2.y += w * v2.y; a2.z += w * v2.z; a2.w += w * v2.w;
        a3.x += w * v3.x; a3.y += w * v3.y; a3.z += w * v3.z; a3.w += w * v3.w;
    }
    float4* o = (float4*)(g_P + idx * 16);
    o[0] = a0; o[1] = a1; o[2] = a2; o[3] = a3;
}

// W1t[m, n]: m in [0,4096) hidden (16,16,16), n in [0,1024) embed (8,16,8)
// one thread -> 8 consecutive n (full n3 range), shared g_P row.
__global__ void w1t_kernel(const float* __restrict__ c2) {
    __shared__ float s[16 * 16 * 8];   // [r2][m3][n3]
    for (int i = threadIdx.x; i < 2048; i += blockDim.x) {
        int r2 = i >> 7, n3 = (i >> 4) & 7, m3 = i & 15;   // c2: [r2][n3][m3]
        s[(r2 * 16 + m3) * 8 + n3] = c2[i];
    }
    __syncthreads();
    int idx = blockIdx.x * blockDim.x + threadIdx.x;    // 524288
    int nq = idx & 127;            // n1*16+n2
    int m  = idx >> 7;
    int n1 = nq >> 4, n2 = nq & 15;
    int m1 = m >> 8, m2 = (m >> 4) & 15, m3 = m & 15;
    const float4* p4 = (const float4*)(g_P +
        (((n1 * 16 + m1) * 256) + (n2 * 16 + m2)) * 16);
    float pv[16];
    *(float4*)&pv[0]  = p4[0]; *(float4*)&pv[4]  = p4[1];
    *(float4*)&pv[8]  = p4[2]; *(float4*)&pv[12] = p4[3];
    float acc[8] = {0, 0, 0, 0, 0, 0, 0, 0};
#pragma unroll
    for (int r2 = 0; r2 < 16; ++r2) {
        const float* sr = s + (r2 * 16 + m3) * 8;
#pragma unroll
        for (int j = 0; j < 8; ++j) acc[j] += pv[r2] * sr[j];
    }
    float4 o0, o1;
    o0.x = to_tf32(acc[0]); o0.y = to_tf32(acc[1]);
    o0.z = to_tf32(acc[2]); o0.w = to_tf32(acc[3]);
    o1.x = to_tf32(acc[4]); o1.y = to_tf32(acc[5]);
    o1.z = to_tf32(acc[6]); o1.w = to_tf32(acc[7]);
    float4* o = (float4*)(g_W1t + (size_t)m * 1024 + nq * 8);
    o[0] = o0; o[1] = o1;
}

// W2t[m, n]: m in [0,1024) embed (8,16,8), n in [0,4096) hidden (16,16,16)
__global__ void w2t_kernel(const float* __restrict__ c2) {
    __shared__ float s[16 * 8 * 16];   // [r2][m3][n3]
    for (int i = threadIdx.x; i < 2048; i += blockDim.x) {
        int r2 = i >> 7, n3 = (i >> 3) & 15, m3 = i & 7;   // c2: [r2][n3][m3]
        s[(r2 * 8 + m3) * 16 + n3] = c2[i];
    }
    __syncthreads();
    int idx = blockIdx.x * blockDim.x + threadIdx.x;    // 524288
    int nh = idx & 511;            // n >> 3
    int m  = idx >> 9;
    int n1 = nh >> 5, n2 = (nh >> 1) & 15, n3b = (nh & 1) * 8;
    int m1 = m >> 7, m2 = (m >> 3) & 15, m3 = m & 7;
    const float4* p4 = (const float4*)(g_P +
        (((n1 * 8 + m1) * 256) + (n2 * 16 + m2)) * 16);
    float pv[16];
    *(float4*)&pv[0]  = p4[0]; *(float4*)&pv[4]  = p4[1];
    *(float4*)&pv[8]  = p4[2]; *(float4*)&pv[12] = p4[3];
    float acc[8] = {0, 0, 0, 0, 0, 0, 0, 0};
#pragma unroll
    for (int r2 = 0; r2 < 16; ++r2) {
        const float* sr = s + (r2 * 8 + m3) * 16 + n3b;
#pragma unroll
        for (int j = 0; j < 8; ++j) acc[j] += pv[r2] * sr[j];
    }
    float4 o0, o1;
    o0.x = to_tf32(acc[0]); o0.y = to_tf32(acc[1]);
    o0.z = to_tf32(acc[2]); o0.w = to_tf32(acc[3]);
    o1.x = to_tf32(acc[4]); o1.y = to_tf32(acc[5]);
    o1.z = to_tf32(acc[6]); o1.w = to_tf32(acc[7]);
    float4* o = (float4*)(g_W2t + (size_t)m * 4096 + nh * 8);
    o[0] = o0; o[1] = o1;
}

__global__ void xround_kernel(const float4* __restrict__ x, float4* __restrict__ o) {
    int i = blockIdx.x * blockDim.x + threadIdx.x;
    float4 v = x[i];
    v.x = to_tf32(v.x); v.y = to_tf32(v.y);
    v.z = to_tf32(v.z); v.w = to_tf32(v.w);
    o[i] = v;
}

// ------------------------------- tf32 GEMM --------------------------------
// C[M,N] = A[M,K] * B[N,K]^T + bias.  fuse=1: C = tf32(gelu_exact(.)).
// 128x128 CTA tile, BK=32, 8 warps (warp tile 64x32), 3-stage cp.async,
// SW128-swizzled smem, ldmatrix.x4 fragment loads.
#define STAGE_B 32768                     // bytes per stage (A 16K + B 16K)

__global__ void __launch_bounds__(256, 2) gemm_tf32(
    const float* __restrict__ A, const float* __restrict__ B,
    const float* __restrict__ bias, float* __restrict__ C,
    int K, int N, int fuse) {
    extern __shared__ char smem[];
    uint32_t sb = smem_u32(smem);

    int tid  = threadIdx.x;
    int lane = tid & 31;
    int q    = lane & 3;
    int g8   = lane >> 2;
    int warp = tid >> 5;
    int wm   = (warp & 1) * 64;
    int wn   = (warp >> 1) * 32;

    size_t rowBase = (size_t)blockIdx.y * 128;
    size_t colBase = (size_t)blockIdx.x * 128;
    const float* Ag = A + rowBase * (size_t)K;
    const float* Bg = B + colBase * (size_t)K;

    // cp.async slot: element id = tid + 256*i -> row, 16B chunk
    // dst = stage + r*128 + ((j ^ (r&7))<<4)
#define LOAD_STAGE(s, buf) do {                                              \
    uint32_t stg = sb + (uint32_t)(buf) * STAGE_B;                           \
    size_t koff = (size_t)(s) * 32;                                          \
    _Pragma("unroll")                                                        \
    for (int i = 0; i < 4; ++i) {                                            \
        int id = tid + 256 * i;                                              \
        int r = id >> 3, j = id & 7;                                         \
        uint32_t off = (uint32_t)(r * 128 + ((j ^ (r & 7)) << 4));           \
        cp16(stg + off,         Ag + (size_t)r * K + koff + j * 4);          \
        cp16(stg + 16384 + off, Bg + (size_t)r * K + koff + j * 4);          \
    }                                                                        \
    CP_COMMIT();                                                             \
} while (0)

    // ldmatrix per-lane geometry
    int rA = ((lane >> 3) & 1) * 8 + (lane & 7);   // A: row-in-slab
    int cA = (lane >> 4) & 1;                      // A: chunk half
    int rB = ((lane >> 4) & 1) * 8 + (lane & 7);   // B: row-in-slab
    int cB = (lane >> 3) & 1;                      // B: chunk half

    uint32_t aBase[4], aSwz[4], bBase[2], bSwz[2];
#pragma unroll
    for (int mt = 0; mt < 4; ++mt) {
        int row = wm + mt * 16 + rA;
        aBase[mt] = (uint32_t)(row * 128);
        aSwz[mt]  = (uint32_t)(row & 7);
    }
#pragma unroll
    for (int p = 0; p < 2; ++p) {
        int row = wn + p * 16 + rB;
        bBase[p] = (uint32_t)(16384 + row * 128);
        bSwz[p]  = (uint32_t)(row & 7);
    }

    float acc[4][4][4];
#pragma unroll
    for (int i = 0; i < 4; ++i)
#pragma unroll
        for (int j = 0; j < 4; ++j)
#pragma unroll
            for (int k = 0; k < 4; ++k) acc[i][j][k] = 0.f;

    int nS = K >> 5;
    LOAD_STAGE(0, 0);
    LOAD_STAGE(1, 1);

    int buf = 0;     // stage holding chunk s
    for (int s = 0; s < nS; ++s) {
        if (s + 2 < nS) CP_WAIT(1); else CP_WAIT(0);
        __syncthreads();
        if (s + 2 < nS) {
            int nb = buf - 1; if (nb < 0) nb += 3;    // (s+2)%3
            LOAD_STAGE(s + 2, nb);
        }

        uint32_t stg = sb + (uint32_t)buf * STAGE_B;
#pragma unroll
        for (int ks = 0; ks < 4; ++ks) {
            uint32_t af[4][4], bf[4][2];
#pragma unroll
            for (int mt = 0; mt < 4; ++mt) {
                uint32_t ad = stg + aBase[mt] +
                              ((((uint32_t)(ks * 2) + cA) ^ aSwz[mt]) << 4);
                ldsm4(af[mt][0], af[mt][1], af[mt][2], af[mt][3], ad);
            }
#pragma unroll
            for (int p = 0; p < 2; ++p) {
                uint32_t bd = stg + bBase[p] +
                              ((((uint32_t)(ks * 2) + cB) ^ bSwz[p]) << 4);
                ldsm4(bf[2 * p][0], bf[2 * p][1],
                      bf[2 * p + 1][0], bf[2 * p + 1][1], bd);
            }
#pragma unroll
            for (int mt = 0; mt < 4; ++mt)
#pragma unroll
                for (int nt = 0; nt < 4; ++nt)
                    mma_tf32(acc[mt][nt], af[mt], bf[nt]);
        }
        buf = (buf == 2) ? 0 : buf + 1;
    }

    // ---- epilogue: bias (+ exact-erf GELU + tf32 round), float2 stores ----
#pragma unroll
    for (int nt = 0; nt < 4; ++nt) {
        int col = (int)colBase + wn + nt * 8 + 2 * q;
        float bx = bias[col], by = bias[col + 1];
#pragma unroll
        for (int mt = 0; mt < 4; ++mt) {
            size_t row0 = rowBase + wm + mt * 16 + g8;
            float v0 = acc[mt][nt][0] + bx;
            float v1 = acc[mt][nt][1] + by;
            float v2 = acc[mt][nt][2] + bx;
            float v3 = acc[mt][nt][3] + by;
            if (fuse) {
                v0 = to_tf32(0.5f * v0 * (1.0f + erff(v0 * 0.70710678118654752f)));
                v1 = to_tf32(0.5f * v1 * (1.0f + erff(v1 * 0.70710678118654752f)));
                v2 = to_tf32(0.5f * v2 * (1.0f + erff(v2 * 0.70710678118654752f)));
                v3 = to_tf32(0.5f * v3 * (1.0f + erff(v3 * 0.70710678118654752f)));
            }
            *(float2*)&C[row0 * (size_t)N + col]       = make_float2(v0, v1);
            *(float2*)&C[(row0 + 8) * (size_t)N + col] = make_float2(v2, v3);
        }
    }
#undef LOAD_STAGE
}

// --------------------------------- launch ---------------------------------
extern "C" void kernel_launch(void* const* d_in, const int* in_sizes, int n_in,
                              void* d_out, int out_size) {
    const float* x   = (const float*)d_in[0];
    const float* c10 = (const float*)d_in[1];
    const float* c11 = (const float*)d_in[2];
    const float* c12 = (const float*)d_in[3];
    const float* b1  = (const float*)d_in[4];
    const float* c20 = (const float*)d_in[5];
    const float* c21 = (const float*)d_in[6];
    const float* c22 = (const float*)d_in[7];
    const float* b2  = (const float*)d_in[8];
    float* out = (float*)d_out;

    float *pW1t, *pW2t, *pH, *pXr;
    cudaGetSymbolAddress((void**)&pW1t, g_W1t);
    cudaGetSymbolAddress((void**)&pW2t, g_W2t);
    cudaGetSymbolAddress((void**)&pH,   g_H);
    cudaGetSymbolAddress((void**)&pXr,  g_Xr);

    const int SMEM = 3 * STAGE_B;   // 98304
    cudaFuncSetAttribute(gemm_tf32, cudaFuncAttributeMaxDynamicSharedMemorySize,
                         SMEM);

    xround_kernel<<<4096, 256>>>((const float4*)x, (float4*)pXr);

    pair_kernel<<<128, 256>>>(c10, c11);
    w1t_kernel<<<2048, 256>>>(c12);
    pair_kernel<<<128, 256>>>(c20, c21);
    w2t_kernel<<<2048, 256>>>(c22);

    // GEMM1: H = tf32(GELU(Xr @ W1t^T + b1))
    gemm_tf32<<<dim3(32, 32), 256, SMEM>>>(pXr, pW1t, b1, pH, 1024, 4096, 1);
    // GEMM2: out = H @ W2t^T + b2
    gemm_tf32<<<dim3(8, 32), 256, SMEM>>>(pH, pW2t, b2, out, 4096, 1024, 0);
}